// round 1
// baseline (speedup 1.0000x reference)
#include <cuda_runtime.h>
#include <math.h>

#define B_    2
#define L_    4096
#define K_    32
#define HALF_ 128
#define NPAIR 28
#define EPSF  1e-6f
#define TWOPI 6.28318530717958647692f
#define BL_   (B_*L_)
#define WARPS 4
#define EPW   8

typedef unsigned long long ull;

__device__ float g_frames[BL_*12];      // e1(3) e2(3) e3(3) t(3), masked
__device__ float g_wsym[NPAIR*HALF_];   // 2pi*(W[mn]+W[nm])
__device__ float g_wv[3*HALF_];         // 2pi*W_vec
__device__ float g_bias[HALF_];         // 2pi*sqrt(EPS)*sum_diag W
__device__ int   g_is64_idx;
__device__ int   g_is64_C;

__constant__ int c_pm[NPAIR] = {0,0,0,0,0,0,0,1,1,1,1,1,1,2,2,2,2,2,3,3,3,3,4,4,4,5,5,6};
__constant__ int c_pn[NPAIR] = {1,2,3,4,5,6,7,2,3,4,5,6,7,3,4,5,6,7,4,5,6,7,5,6,7,6,7,7};

static __device__ __forceinline__ ull pack2(float lo, float hi){
    ull r; asm("mov.b64 %0, {%1,%2};" : "=l"(r) : "f"(lo), "f"(hi)); return r;
}
static __device__ __forceinline__ void unpack2(ull v, float& lo, float& hi){
    asm("mov.b64 {%0,%1}, %2;" : "=f"(lo), "=f"(hi) : "l"(v));
}
static __device__ __forceinline__ ull fma2(ull a, ull b, ull c){
    ull d; asm("fma.rn.f32x2 %0, %1, %2, %3;" : "=l"(d) : "l"(a), "l"(b), "l"(c)); return d;
}
static __device__ __forceinline__ ull mul2(ull a, ull b){
    ull d; asm("mul.rn.f32x2 %0, %1, %2;" : "=l"(d) : "l"(a), "l"(b)); return d;
}
static __device__ __forceinline__ ull dup2(float x){ return pack2(x, x); }

// ---------------------------------------------------------------------------
// dtype detection: int64 buffers have zero odd 32-bit words (values < 4096)
// ---------------------------------------------------------------------------
__global__ void detect_kernel(const int* eidx, const int* Cw){
    if (threadIdx.x == 0){
        int o1 = 0, o2 = 0;
        #pragma unroll
        for (int i = 0; i < 64; i++){ o1 |= eidx[2*i+1]; o2 |= Cw[2*i+1]; }
        g_is64_idx = (o1 == 0);
        g_is64_C   = (o2 == 0);
    }
}

// ---------------------------------------------------------------------------
// W preparation: fold 2pi, symmetrize W_dist over pairs, diagonal bias
// ---------------------------------------------------------------------------
__global__ void wprep_kernel(const float* __restrict__ Wvec, const float* __restrict__ Wdist){
    int e = threadIdx.x;  // 0..127
    #pragma unroll
    for (int d = 0; d < 3; d++) g_wv[d*HALF_ + e] = TWOPI * Wvec[d*HALF_ + e];
    float b = 0.f;
    #pragma unroll
    for (int m = 0; m < 8; m++) b += Wdist[(m*8+m)*HALF_ + e];
    g_bias[e] = TWOPI * sqrtf(EPSF) * b;
    for (int p = 0; p < NPAIR; p++){
        int m = c_pm[p], n = c_pn[p];
        g_wsym[p*HALF_ + e] = TWOPI * (Wdist[(m*8+n)*HALF_ + e] + Wdist[(n*8+m)*HALF_ + e]);
    }
}

// ---------------------------------------------------------------------------
// Per-residue frames: R_i (as e1,e2,e3 columns) and t_i, masked by C>0
// ---------------------------------------------------------------------------
__global__ void frames_kernel(const float* __restrict__ X, const void* __restrict__ Cv){
    int r = blockIdx.x * blockDim.x + threadIdx.x;
    if (r >= BL_) return;
    const float* x = X + (size_t)r * 12;
    float Nx=x[0], Ny=x[1], Nz=x[2];
    float Ax=x[3], Ay=x[4], Az=x[5];
    float Cx=x[6], Cy=x[7], Cz=x[8];
    long long cv = g_is64_C ? ((const long long*)Cv)[r] : (long long)((const int*)Cv)[r];
    float mask = (cv > 0) ? 1.f : 0.f;

    float v1x=Nx-Ax, v1y=Ny-Ay, v1z=Nz-Az;
    float n1 = sqrtf(v1x*v1x + v1y*v1y + v1z*v1z) + EPSF;
    float e1x=v1x/n1, e1y=v1y/n1, e1z=v1z/n1;

    float u2x=Cx-Ax, u2y=Cy-Ay, u2z=Cz-Az;
    float n2 = sqrtf(u2x*u2x + u2y*u2y + u2z*u2z) + EPSF;
    u2x/=n2; u2y/=n2; u2z/=n2;

    float dt = u2x*e1x + u2y*e1y + u2z*e1z;
    float w2x = u2x - dt*e1x, w2y = u2y - dt*e1y, w2z = u2z - dt*e1z;
    float n3 = sqrtf(w2x*w2x + w2y*w2y + w2z*w2z) + EPSF;
    float e2x=w2x/n3, e2y=w2y/n3, e2z=w2z/n3;

    float e3x = e1y*e2z - e1z*e2y;
    float e3y = e1z*e2x - e1x*e2z;
    float e3z = e1x*e2y - e1y*e2x;

    float* f = g_frames + (size_t)r * 12;
    f[0]=mask*e1x; f[1]=mask*e1y; f[2]=mask*e1z;
    f[3]=mask*e2x; f[4]=mask*e2y; f[5]=mask*e2z;
    f[6]=mask*e3x; f[7]=mask*e3y; f[8]=mask*e3z;
    f[9]=mask*Ax;  f[10]=mask*Ay; f[11]=mask*Az;
}

// ---------------------------------------------------------------------------
// Main kernel: one block per residue (128 thr, 4 warps x 8 edges).
// Lane -> 4 output columns; f32x2-packed accumulators.
// ---------------------------------------------------------------------------
__global__ __launch_bounds__(128, 3)
void edge_kernel(const float* __restrict__ X, const void* __restrict__ eidxv,
                 const void* __restrict__ Cv, float* __restrict__ out){
    __shared__ float s_wsym[NPAIR*HALF_];   // 14336 B
    __shared__ float s_wv[3*HALF_];         // 1536 B
    __shared__ float s_bias[HALF_];         // 512 B
    __shared__ float s_fr[12];
    __shared__ float s_xi[12];
    __shared__ float s_xj[K_*12];           // 1536 B
    __shared__ float s_mj[K_];
    __shared__ float s_d[WARPS][EPW*64];    // dup'd distances {d,d} per (e,pair): 8192 B

    int tid  = threadIdx.x;
    int res  = blockIdx.x;
    int bbase = res & ~(L_-1);
    int is64 = g_is64_idx;

    // --- cooperative staging ---
    {
        const float4* src = (const float4*)g_wsym;
        float4* dst = (float4*)s_wsym;
        #pragma unroll
        for (int i = tid; i < NPAIR*HALF_/4; i += 128) dst[i] = src[i];
    }
    if (tid < 96)                 ((float4*)s_wv)[tid]      = ((const float4*)g_wv)[tid];
    if (tid >= 96 && tid < 128)   ((float4*)s_bias)[tid-96] = ((const float4*)g_bias)[tid-96];
    if (tid < 3)                  ((float4*)s_fr)[tid]      = ((const float4*)g_frames)[res*3 + tid];
    if (tid >= 4 && tid < 7)      ((float4*)s_xi)[tid-4]    = ((const float4*)X)[res*3 + (tid-4)];
    if (tid < K_*3){
        int kk = tid/3, part = tid - kk*3;
        long long j = is64 ? ((const long long*)eidxv)[res*K_ + kk]
                           : (long long)((const int*)eidxv)[res*K_ + kk];
        int jg = bbase + (int)j;
        ((float4*)&s_xj[kk*12])[part] = ((const float4*)X)[jg*3 + part];
    }
    if (tid >= 96 && tid < 96 + K_){
        int kk = tid - 96;
        long long j = is64 ? ((const long long*)eidxv)[res*K_ + kk]
                           : (long long)((const int*)eidxv)[res*K_ + kk];
        int jg = bbase + (int)j;
        long long cval = g_is64_C ? ((const long long*)Cv)[jg]
                                  : (long long)((const int*)Cv)[jg];
        s_mj[kk] = (cval > 0) ? 1.f : 0.f;
    }
    __syncthreads();

    int w = tid >> 5, lane = tid & 31;
    int ebase = w * EPW;
    int col = lane * 4;

    // --- distances: lane p computes pair p for all 8 edges ---
    if (lane < NPAIR){
        int m = c_pm[lane], n = c_pn[lane];
        bool mI = (m < 4), nI = (n < 4);
        float mx=0.f,my=0.f,mz=0.f, nx=0.f,ny=0.f,nz=0.f;
        if (mI){ mx=s_xi[m*3]; my=s_xi[m*3+1]; mz=s_xi[m*3+2]; }
        if (nI){ nx=s_xi[n*3]; ny=s_xi[n*3+1]; nz=s_xi[n*3+2]; }
        #pragma unroll
        for (int e = 0; e < EPW; e++){
            const float* xj = &s_xj[(ebase+e)*12];
            float ax = mI ? mx : xj[(m-4)*3+0];
            float ay = mI ? my : xj[(m-4)*3+1];
            float az = mI ? mz : xj[(m-4)*3+2];
            float bx = nI ? nx : xj[(n-4)*3+0];
            float by = nI ? ny : xj[(n-4)*3+1];
            float bz = nI ? nz : xj[(n-4)*3+2];
            float dx=ax-bx, dy=ay-by, dz=az-bz;
            float dd = fmaf(dx,dx, fmaf(dy,dy, fmaf(dz,dz, EPSF)));
            float dist = __fsqrt_rn(dd);
            ((float2*)&s_d[w][e*64])[lane] = make_float2(dist, dist);
        }
    }
    __syncwarp();

    // --- frames to regs ---
    float e1x=s_fr[0], e1y=s_fr[1], e1z=s_fr[2];
    float e2x=s_fr[3], e2y=s_fr[4], e2z=s_fr[5];
    float e3x=s_fr[6], e3y=s_fr[7], e3z=s_fr[8];
    float tix=s_fr[9], tiy=s_fr[10], tiz=s_fr[11];

    // --- hv = t_ji @ (2pi W_vec) ---
    ull hv_a[EPW], hv_b[EPW];
    float4 v0 = *(const float4*)&s_wv[0*HALF_ + col];
    float4 v1 = *(const float4*)&s_wv[1*HALF_ + col];
    float4 v2 = *(const float4*)&s_wv[2*HALF_ + col];
    ull v0a=pack2(v0.x,v0.y), v0b=pack2(v0.z,v0.w);
    ull v1a=pack2(v1.x,v1.y), v1b=pack2(v1.z,v1.w);
    ull v2a=pack2(v2.x,v2.y), v2b=pack2(v2.z,v2.w);
    #pragma unroll
    for (int e = 0; e < EPW; e++){
        int k = ebase + e;
        float mj = s_mj[k];
        float dx = mj*s_xj[k*12+3] - tix;
        float dy = mj*s_xj[k*12+4] - tiy;
        float dz = mj*s_xj[k*12+5] - tiz;
        float t0 = fmaf(e1z,dz, fmaf(e1y,dy, e1x*dx));
        float t1 = fmaf(e2z,dz, fmaf(e2y,dy, e2x*dx));
        float t2 = fmaf(e3z,dz, fmaf(e3y,dy, e3x*dx));
        ull t0d = dup2(t0), t1d = dup2(t1), t2d = dup2(t2);
        hv_a[e] = fma2(t2d, v2a, fma2(t1d, v1a, mul2(t0d, v0a)));
        hv_b[e] = fma2(t2d, v2b, fma2(t1d, v1b, mul2(t0d, v0b)));
    }

    // --- hd = bias + sum_p D_p * Wsym_p ---
    ull hd_a[EPW], hd_b[EPW];
    float4 bq = *(const float4*)&s_bias[col];
    ull bqa = pack2(bq.x,bq.y), bqb = pack2(bq.z,bq.w);
    #pragma unroll
    for (int e = 0; e < EPW; e++){ hd_a[e]=bqa; hd_b[e]=bqb; }

    #pragma unroll 2
    for (int pp = 0; pp < NPAIR; pp += 2){
        float4 w0 = *(const float4*)&s_wsym[pp*HALF_ + col];
        float4 w1 = *(const float4*)&s_wsym[(pp+1)*HALF_ + col];
        ull w0a=pack2(w0.x,w0.y), w0b=pack2(w0.z,w0.w);
        ull w1a=pack2(w1.x,w1.y), w1b=pack2(w1.z,w1.w);
        #pragma unroll
        for (int e = 0; e < EPW; e++){
            float4 dq = *(const float4*)&s_d[w][e*64 + pp*2];  // {dp,dp,dp+1,dp+1} broadcast
            ull da = pack2(dq.x,dq.y), db = pack2(dq.z,dq.w);
            hd_a[e] = fma2(da, w0a, hd_a[e]);
            hd_b[e] = fma2(da, w0b, hd_b[e]);
            hd_a[e] = fma2(db, w1a, hd_a[e]);
            hd_b[e] = fma2(db, w1b, hd_b[e]);
        }
    }

    // --- epilogue: cos/sin sums, coalesced float4 stores ---
    #pragma unroll
    for (int e = 0; e < EPW; e++){
        float a0,a1,a2,a3, b0,b1,b2,b3;
        unpack2(hv_a[e], a0, a1); unpack2(hv_b[e], a2, a3);
        unpack2(hd_a[e], b0, b1); unpack2(hd_b[e], b2, b3);
        float sv0,cv0,sv1,cv1,sv2,cv2,sv3,cv3;
        float sd0,cd0,sd1,cd1,sd2,cd2,sd3,cd3;
        __sincosf(a0,&sv0,&cv0); __sincosf(a1,&sv1,&cv1);
        __sincosf(a2,&sv2,&cv2); __sincosf(a3,&sv3,&cv3);
        __sincosf(b0,&sd0,&cd0); __sincosf(b1,&sd1,&cd1);
        __sincosf(b2,&sd2,&cd2); __sincosf(b3,&sd3,&cd3);
        size_t obase = ((size_t)(res*K_ + ebase + e))*256 + col;
        *(float4*)&out[obase]       = make_float4(cv0+cd0, cv1+cd1, cv2+cd2, cv3+cd3);
        *(float4*)&out[obase + 128] = make_float4(sv0+sd0, sv1+sd1, sv2+sd2, sv3+sd3);
    }
}

// ---------------------------------------------------------------------------
extern "C" void kernel_launch(void* const* d_in, const int* in_sizes, int n_in,
                              void* d_out, int out_size){
    const float* X     = (const float*)d_in[0];
    const void*  eidx  = d_in[1];
    const void*  C     = d_in[2];
    const float* Wvec  = (const float*)d_in[3];
    const float* Wdist = (const float*)d_in[4];
    (void)in_sizes; (void)n_in; (void)out_size;

    detect_kernel<<<1, 32>>>((const int*)eidx, (const int*)C);
    wprep_kernel<<<1, 128>>>(Wvec, Wdist);
    frames_kernel<<<BL_/256, 256>>>(X, C);
    edge_kernel<<<BL_, 128>>>(X, eidx, C, (float*)d_out);
}

// round 4
// speedup vs baseline: 1.1212x; 1.1212x over previous
#include <cuda_runtime.h>
#include <math.h>

#define B_    2
#define L_    4096
#define K_    32
#define HALF_ 128
#define NPAIR 28
#define EPSF  1e-6f
#define TWOPI 6.28318530717958647692f
#define BL_   (B_*L_)
#define NW    8
#define EPW   4

typedef unsigned long long ull;

__device__ float g_wsym[NPAIR*HALF_];   // 2pi*(W[mn]+W[nm])
__device__ float g_wv[3*HALF_];         // 2pi*W_vec
__device__ float g_bias[HALF_];         // 2pi*sqrt(EPS)*sum_diag W
__device__ int   g_is64_idx;
__device__ int   g_is64_C;

__constant__ int c_pm[NPAIR] = {0,0,0,0,0,0,0,1,1,1,1,1,1,2,2,2,2,2,3,3,3,3,4,4,4,5,5,6};
__constant__ int c_pn[NPAIR] = {1,2,3,4,5,6,7,2,3,4,5,6,7,3,4,5,6,7,4,5,6,7,5,6,7,6,7,7};

static __device__ __forceinline__ ull pack2(float lo, float hi){
    ull r; asm("mov.b64 %0, {%1,%2};" : "=l"(r) : "f"(lo), "f"(hi)); return r;
}
static __device__ __forceinline__ void unpack2(ull v, float& lo, float& hi){
    asm("mov.b64 {%0,%1}, %2;" : "=f"(lo), "=f"(hi) : "l"(v));
}
static __device__ __forceinline__ ull fma2(ull a, ull b, ull c){
    ull d; asm("fma.rn.f32x2 %0, %1, %2, %3;" : "=l"(d) : "l"(a), "l"(b), "l"(c)); return d;
}
static __device__ __forceinline__ ull mul2(ull a, ull b){
    ull d; asm("mul.rn.f32x2 %0, %1, %2;" : "=l"(d) : "l"(a), "l"(b)); return d;
}
static __device__ __forceinline__ ull dup2(float x){ return pack2(x, x); }

// ---------------------------------------------------------------------------
// dtype detection: int64 buffers have zero odd 32-bit words (values < 4096)
// ---------------------------------------------------------------------------
__global__ void detect_kernel(const int* eidx, const int* Cw){
    if (threadIdx.x == 0){
        int o1 = 0, o2 = 0;
        #pragma unroll
        for (int i = 0; i < 64; i++){ o1 |= eidx[2*i+1]; o2 |= Cw[2*i+1]; }
        g_is64_idx = (o1 == 0);
        g_is64_C   = (o2 == 0);
    }
}

// ---------------------------------------------------------------------------
// W preparation: fold 2pi, symmetrize W_dist over pairs, diagonal bias
// ---------------------------------------------------------------------------
__global__ void wprep_kernel(const float* __restrict__ Wvec, const float* __restrict__ Wdist){
    int e = threadIdx.x;  // 0..127
    #pragma unroll
    for (int d = 0; d < 3; d++) g_wv[d*HALF_ + e] = TWOPI * Wvec[d*HALF_ + e];
    float b = 0.f;
    #pragma unroll
    for (int m = 0; m < 8; m++) b += Wdist[(m*8+m)*HALF_ + e];
    g_bias[e] = TWOPI * sqrtf(EPSF) * b;
    for (int p = 0; p < NPAIR; p++){
        int m = c_pm[p], n = c_pn[p];
        g_wsym[p*HALF_ + e] = TWOPI * (Wdist[(m*8+n)*HALF_ + e] + Wdist[(n*8+m)*HALF_ + e]);
    }
}

// ---------------------------------------------------------------------------
// Main kernel: one block per residue (256 thr, 8 warps x 4 edges).
// hd pair-loop first (lean accumulators), then fused hv + sincos + store.
// ---------------------------------------------------------------------------
__global__ __launch_bounds__(256, 3)
void edge_kernel(const float* __restrict__ X, const void* __restrict__ eidxv,
                 const void* __restrict__ Cv, float* __restrict__ out){
    __shared__ float s_wsym[NPAIR*HALF_];   // 14336 B
    __shared__ float s_wv[3*HALF_];         // 1536 B
    __shared__ float s_bias[HALF_];         // 512 B
    __shared__ float s_fr[12];
    __shared__ float s_xi[12];
    __shared__ float s_xj[K_*12];           // 1536 B
    __shared__ float s_mj[K_];
    __shared__ float s_d[NW][EPW*NPAIR];    // 3584 B, non-duplicated

    int tid  = threadIdx.x;
    int res  = blockIdx.x;
    int bbase = res & ~(L_-1);
    int is64 = g_is64_idx;

    // --- cooperative staging ---
    {
        const float4* src = (const float4*)g_wsym;
        float4* dst = (float4*)s_wsym;
        #pragma unroll
        for (int i = tid; i < NPAIR*HALF_/4; i += 256) dst[i] = src[i];
    }
    if (tid < 96)                  ((float4*)s_wv)[tid]      = ((const float4*)g_wv)[tid];
    if (tid >= 96 && tid < 128)    ((float4*)s_bias)[tid-96] = ((const float4*)g_bias)[tid-96];
    if (tid >= 128 && tid < 128 + K_*3){
        int t = tid - 128;
        int kk = t/3, part = t - kk*3;
        long long j = is64 ? ((const long long*)eidxv)[res*K_ + kk]
                           : (long long)((const int*)eidxv)[res*K_ + kk];
        ((float4*)&s_xj[kk*12])[part] = ((const float4*)X)[(bbase + (int)j)*3 + part];
    }
    if (tid >= 224 && tid < 224 + K_){
        int kk = tid - 224;
        long long j = is64 ? ((const long long*)eidxv)[res*K_ + kk]
                           : (long long)((const int*)eidxv)[res*K_ + kk];
        int jg = bbase + (int)j;
        long long cval = g_is64_C ? ((const long long*)Cv)[jg]
                                  : (long long)((const int*)Cv)[jg];
        s_mj[kk] = (cval > 0) ? 1.f : 0.f;
    }
    if (tid < 3) ((float4*)s_xi)[tid] = ((const float4*)X)[res*3 + tid];
    if (tid == 3){
        // frames for own residue (inline; t_j needs only masked CA_j)
        const float* x = X + (size_t)res * 12;
        float Nx=x[0], Ny=x[1], Nz=x[2];
        float Ax=x[3], Ay=x[4], Az=x[5];
        float Cx=x[6], Cy=x[7], Cz=x[8];
        long long cv = g_is64_C ? ((const long long*)Cv)[res] : (long long)((const int*)Cv)[res];
        float mask = (cv > 0) ? 1.f : 0.f;

        float v1x=Nx-Ax, v1y=Ny-Ay, v1z=Nz-Az;
        float n1 = sqrtf(v1x*v1x + v1y*v1y + v1z*v1z) + EPSF;
        float e1x=v1x/n1, e1y=v1y/n1, e1z=v1z/n1;

        float u2x=Cx-Ax, u2y=Cy-Ay, u2z=Cz-Az;
        float n2 = sqrtf(u2x*u2x + u2y*u2y + u2z*u2z) + EPSF;
        u2x/=n2; u2y/=n2; u2z/=n2;

        float dt = u2x*e1x + u2y*e1y + u2z*e1z;
        float w2x = u2x - dt*e1x, w2y = u2y - dt*e1y, w2z = u2z - dt*e1z;
        float n3 = sqrtf(w2x*w2x + w2y*w2y + w2z*w2z) + EPSF;
        float e2x=w2x/n3, e2y=w2y/n3, e2z=w2z/n3;

        float e3x = e1y*e2z - e1z*e2y;
        float e3y = e1z*e2x - e1x*e2z;
        float e3z = e1x*e2y - e1y*e2x;

        s_fr[0]=mask*e1x; s_fr[1]=mask*e1y; s_fr[2]=mask*e1z;
        s_fr[3]=mask*e2x; s_fr[4]=mask*e2y; s_fr[5]=mask*e2z;
        s_fr[6]=mask*e3x; s_fr[7]=mask*e3y; s_fr[8]=mask*e3z;
        s_fr[9]=mask*Ax;  s_fr[10]=mask*Ay; s_fr[11]=mask*Az;
    }
    __syncthreads();

    int w = tid >> 5, lane = tid & 31;
    int ebase = w * EPW;
    int col = lane * 4;

    // --- distances: lane p computes pair p for this warp's 4 edges ---
    if (lane < NPAIR){
        int m = c_pm[lane], n = c_pn[lane];
        bool mI = (m < 4), nI = (n < 4);
        float mx=0.f,my=0.f,mz=0.f, nx=0.f,ny=0.f,nz=0.f;
        if (mI){ mx=s_xi[m*3]; my=s_xi[m*3+1]; mz=s_xi[m*3+2]; }
        if (nI){ nx=s_xi[n*3]; ny=s_xi[n*3+1]; nz=s_xi[n*3+2]; }
        #pragma unroll
        for (int e = 0; e < EPW; e++){
            const float* xj = &s_xj[(ebase+e)*12];
            float ax = mI ? mx : xj[(m-4)*3+0];
            float ay = mI ? my : xj[(m-4)*3+1];
            float az = mI ? mz : xj[(m-4)*3+2];
            float bx = nI ? nx : xj[(n-4)*3+0];
            float by = nI ? ny : xj[(n-4)*3+1];
            float bz = nI ? nz : xj[(n-4)*3+2];
            float dx=ax-bx, dy=ay-by, dz=az-bz;
            float dd = fmaf(dx,dx, fmaf(dy,dy, fmaf(dz,dz, EPSF)));
            s_d[w][e*NPAIR + lane] = __fsqrt_rn(dd);
        }
    }
    __syncwarp();

    // --- hd = bias + sum_p D_p * Wsym_p (4 cols as 2 f32x2 accumulators x 4 edges) ---
    ull hd_a[EPW], hd_b[EPW];
    {
        float4 bq = *(const float4*)&s_bias[col];
        ull bqa = pack2(bq.x,bq.y), bqb = pack2(bq.z,bq.w);
        #pragma unroll
        for (int e = 0; e < EPW; e++){ hd_a[e]=bqa; hd_b[e]=bqb; }
    }
    #pragma unroll 1
    for (int pp = 0; pp < NPAIR; pp += 4){
        float4 w0 = *(const float4*)&s_wsym[(pp+0)*HALF_ + col];
        float4 w1 = *(const float4*)&s_wsym[(pp+1)*HALF_ + col];
        float4 w2 = *(const float4*)&s_wsym[(pp+2)*HALF_ + col];
        float4 w3 = *(const float4*)&s_wsym[(pp+3)*HALF_ + col];
        ull w0a=pack2(w0.x,w0.y), w0b=pack2(w0.z,w0.w);
        ull w1a=pack2(w1.x,w1.y), w1b=pack2(w1.z,w1.w);
        ull w2a=pack2(w2.x,w2.y), w2b=pack2(w2.z,w2.w);
        ull w3a=pack2(w3.x,w3.y), w3b=pack2(w3.z,w3.w);
        float4 dq0 = *(const float4*)&s_d[w][0*NPAIR + pp];
        float4 dq1 = *(const float4*)&s_d[w][1*NPAIR + pp];
        float4 dq2 = *(const float4*)&s_d[w][2*NPAIR + pp];
        float4 dq3 = *(const float4*)&s_d[w][3*NPAIR + pp];
        {
            ull d0=dup2(dq0.x), d1=dup2(dq0.y), d2=dup2(dq0.z), d3=dup2(dq0.w);
            hd_a[0]=fma2(d0,w0a,hd_a[0]); hd_b[0]=fma2(d0,w0b,hd_b[0]);
            hd_a[0]=fma2(d1,w1a,hd_a[0]); hd_b[0]=fma2(d1,w1b,hd_b[0]);
            hd_a[0]=fma2(d2,w2a,hd_a[0]); hd_b[0]=fma2(d2,w2b,hd_b[0]);
            hd_a[0]=fma2(d3,w3a,hd_a[0]); hd_b[0]=fma2(d3,w3b,hd_b[0]);
        }
        {
            ull d0=dup2(dq1.x), d1=dup2(dq1.y), d2=dup2(dq1.z), d3=dup2(dq1.w);
            hd_a[1]=fma2(d0,w0a,hd_a[1]); hd_b[1]=fma2(d0,w0b,hd_b[1]);
            hd_a[1]=fma2(d1,w1a,hd_a[1]); hd_b[1]=fma2(d1,w1b,hd_b[1]);
            hd_a[1]=fma2(d2,w2a,hd_a[1]); hd_b[1]=fma2(d2,w2b,hd_b[1]);
            hd_a[1]=fma2(d3,w3a,hd_a[1]); hd_b[1]=fma2(d3,w3b,hd_b[1]);
        }
        {
            ull d0=dup2(dq2.x), d1=dup2(dq2.y), d2=dup2(dq2.z), d3=dup2(dq2.w);
            hd_a[2]=fma2(d0,w0a,hd_a[2]); hd_b[2]=fma2(d0,w0b,hd_b[2]);
            hd_a[2]=fma2(d1,w1a,hd_a[2]); hd_b[2]=fma2(d1,w1b,hd_b[2]);
            hd_a[2]=fma2(d2,w2a,hd_a[2]); hd_b[2]=fma2(d2,w2b,hd_b[2]);
            hd_a[2]=fma2(d3,w3a,hd_a[2]); hd_b[2]=fma2(d3,w3b,hd_b[2]);
        }
        {
            ull d0=dup2(dq3.x), d1=dup2(dq3.y), d2=dup2(dq3.z), d3=dup2(dq3.w);
            hd_a[3]=fma2(d0,w0a,hd_a[3]); hd_b[3]=fma2(d0,w0b,hd_b[3]);
            hd_a[3]=fma2(d1,w1a,hd_a[3]); hd_b[3]=fma2(d1,w1b,hd_b[3]);
            hd_a[3]=fma2(d2,w2a,hd_a[3]); hd_b[3]=fma2(d2,w2b,hd_b[3]);
            hd_a[3]=fma2(d3,w3a,hd_a[3]); hd_b[3]=fma2(d3,w3b,hd_b[3]);
        }
    }

    // --- fused epilogue: hv, sincos, store (per edge; keeps regs lean) ---
    float e1x=s_fr[0], e1y=s_fr[1], e1z=s_fr[2];
    float e2x=s_fr[3], e2y=s_fr[4], e2z=s_fr[5];
    float e3x=s_fr[6], e3y=s_fr[7], e3z=s_fr[8];
    float tix=s_fr[9], tiy=s_fr[10], tiz=s_fr[11];
    float4 v0 = *(const float4*)&s_wv[0*HALF_ + col];
    float4 v1 = *(const float4*)&s_wv[1*HALF_ + col];
    float4 v2 = *(const float4*)&s_wv[2*HALF_ + col];
    ull v0a=pack2(v0.x,v0.y), v0b=pack2(v0.z,v0.w);
    ull v1a=pack2(v1.x,v1.y), v1b=pack2(v1.z,v1.w);
    ull v2a=pack2(v2.x,v2.y), v2b=pack2(v2.z,v2.w);

    #pragma unroll
    for (int e = 0; e < EPW; e++){
        int k = ebase + e;
        float mj = s_mj[k];
        float dx = fmaf(mj, s_xj[k*12+3], -tix);
        float dy = fmaf(mj, s_xj[k*12+4], -tiy);
        float dz = fmaf(mj, s_xj[k*12+5], -tiz);
        float t0 = fmaf(e1z,dz, fmaf(e1y,dy, e1x*dx));
        float t1 = fmaf(e2z,dz, fmaf(e2y,dy, e2x*dx));
        float t2 = fmaf(e3z,dz, fmaf(e3y,dy, e3x*dx));
        ull t0d = dup2(t0), t1d = dup2(t1), t2d = dup2(t2);
        ull hv_a = fma2(t2d, v2a, fma2(t1d, v1a, mul2(t0d, v0a)));
        ull hv_b = fma2(t2d, v2b, fma2(t1d, v1b, mul2(t0d, v0b)));

        float a0,a1,a2,a3, b0,b1,b2,b3;
        unpack2(hv_a, a0, a1); unpack2(hv_b, a2, a3);
        unpack2(hd_a[e], b0, b1); unpack2(hd_b[e], b2, b3);
        float sv0,cv0,sv1,cv1,sv2,cv2,sv3,cv3;
        float sd0,cd0,sd1,cd1,sd2,cd2,sd3,cd3;
        __sincosf(a0,&sv0,&cv0); __sincosf(a1,&sv1,&cv1);
        __sincosf(a2,&sv2,&cv2); __sincosf(a3,&sv3,&cv3);
        __sincosf(b0,&sd0,&cd0); __sincosf(b1,&sd1,&cd1);
        __sincosf(b2,&sd2,&cd2); __sincosf(b3,&sd3,&cd3);
        size_t obase = ((size_t)(res*K_ + k))*256 + col;
        __stcs((float4*)&out[obase],       make_float4(cv0+cd0, cv1+cd1, cv2+cd2, cv3+cd3));
        __stcs((float4*)&out[obase + 128], make_float4(sv0+sd0, sv1+sd1, sv2+sd2, sv3+sd3));
    }
}

// ---------------------------------------------------------------------------
extern "C" void kernel_launch(void* const* d_in, const int* in_sizes, int n_in,
                              void* d_out, int out_size){
    const float* X     = (const float*)d_in[0];
    const void*  eidx  = d_in[1];
    const void*  C     = d_in[2];
    const float* Wvec  = (const float*)d_in[3];
    const float* Wdist = (const float*)d_in[4];
    (void)in_sizes; (void)n_in; (void)out_size;

    detect_kernel<<<1, 32>>>((const int*)eidx, (const int*)C);
    wprep_kernel<<<1, 128>>>(Wvec, Wdist);
    edge_kernel<<<BL_, 256>>>(X, eidx, C, (float*)d_out);
}